// round 1
// baseline (speedup 1.0000x reference)
#include <cuda_runtime.h>

// Problem constants
#define BB 4
#define CC 256
#define HWIN 1024      // 32*32
#define NQ 4225        // 65*65
#define NK 1024
#define NCO 192        // 128 shortcut + 64 q

typedef unsigned long long ull;

// ---------------- scratch (device globals; no allocation allowed) -----------
__device__ float g_xr[BB * CC * HWIN];        // BN+ReLU output [b][c][p]
__device__ float g_wt[CC * 9 * NCO];          // repacked conv weights [c][tap][co]
__device__ float g_q[BB * 64 * NQ];           // q conv output  [b][d][n]
__device__ float g_attO[BB * 64 * NQ];        // attention out  [b][d][n]
__device__ float g_kp[BB * 8 * 512 * 16];     // k pair-packed [b][h][j2][d(8)][2]
__device__ float g_vp[BB * 8 * 512 * 16];     // v pair-packed

// ---------------- f32x2 helpers ---------------------------------------------
__device__ __forceinline__ ull pk2(float a, float b) {
    ull r; asm("mov.b64 %0, {%1,%2};" : "=l"(r) : "f"(a), "f"(b)); return r;
}
__device__ __forceinline__ void upk2(ull v, float& a, float& b) {
    asm("mov.b64 {%0,%1}, %2;" : "=f"(a), "=f"(b) : "l"(v));
}
__device__ __forceinline__ ull ffma2(ull a, ull b, ull c) {
    ull r; asm("fma.rn.f32x2 %0, %1, %2, %3;" : "=l"(r) : "l"(a), "l"(b), "l"(c)); return r;
}
__device__ __forceinline__ ull fmul2(ull a, ull b) {
    ull r; asm("mul.rn.f32x2 %0, %1, %2;" : "=l"(r) : "l"(a), "l"(b)); return r;
}
__device__ __forceinline__ float ex2f(float x) {
    float r; asm("ex2.approx.f32 %0, %1;" : "=f"(r) : "f"(x)); return r;
}

// ---------------- kernel 1: BN (inference) + ReLU ----------------------------
__global__ void __launch_bounds__(256) bn_kernel(
    const float* __restrict__ x, const float* __restrict__ gamma,
    const float* __restrict__ beta, const float* __restrict__ rmean,
    const float* __restrict__ rvar)
{
    int idx = blockIdx.x * 256 + threadIdx.x;          // [0, 1048576)
    int c = (idx >> 10) & 255;
    float a = gamma[c] * rsqrtf(rvar[c] + 1e-5f);
    float bia = beta[c] - rmean[c] * a;
    g_xr[idx] = fmaxf(fmaf(x[idx], a, bia), 0.f);
}

// ---------------- kernel 2: repack + FLIP conv-transpose weights -------------
// jax.lax.conv_transpose(transpose_kernel=False) => effective gather tap is the
// spatially flipped kernel: dest tap t uses source tap 8-t.
__global__ void __launch_bounds__(256) repack_kernel(
    const float* __restrict__ w_sc, const float* __restrict__ w_q)
{
    int i = blockIdx.x * 256 + threadIdx.x;            // [0, 442368)
    int c = i / (9 * NCO);
    int r = i - c * (9 * NCO);
    int t = r / NCO;
    int co = r - t * NCO;
    int s = 8 - t;
    float v;
    if (co < 128) v = w_sc[(c * 128 + co) * 9 + s];
    else          v = w_q[(c * 64 + (co - 128)) * 9 + s];
    g_wt[i] = v;
}

// ---------------- kernel 3: k = Wk@xr, v = Wv@xr, pair-packed ----------------
__global__ void __launch_bounds__(256) kv_kernel(
    const float* __restrict__ wk, const float* __restrict__ wv)
{
    const int b = blockIdx.y;
    const int p = blockIdx.x * 32 + (threadIdx.x & 31);
    const int dg = threadIdx.x >> 5;                   // 0..7 (16 d each)
    const float* wbase = (dg < 4) ? (wk + dg * 16 * CC) : (wv + (dg - 4) * 16 * CC);
    const float* xp = g_xr + b * (CC * HWIN) + p;

    float acc[16];
#pragma unroll
    for (int i = 0; i < 16; i++) acc[i] = 0.f;

    for (int c = 0; c < CC; c += 4) {
        float x0 = xp[(c + 0) * HWIN];
        float x1 = xp[(c + 1) * HWIN];
        float x2 = xp[(c + 2) * HWIN];
        float x3 = xp[(c + 3) * HWIN];
#pragma unroll
        for (int i = 0; i < 16; i++) {
            float4 w4 = *(const float4*)(wbase + i * CC + c);
            acc[i] = fmaf(w4.x, x0, fmaf(w4.y, x1, fmaf(w4.z, x2, fmaf(w4.w, x3, acc[i]))));
        }
    }
    const int par = p & 1, j2 = p >> 1;
#pragma unroll
    for (int i = 0; i < 16; i++) {
        int d = dg * 16 + i;
        if (d < 64) {
            int hh = d >> 3, dd = d & 7;
            g_kp[(b * 8 + hh) * 8192 + j2 * 16 + dd * 2 + par] = acc[i];
        } else {
            int d2 = d - 64, hh = d2 >> 3, dd = d2 & 7;
            g_vp[(b * 8 + hh) * 8192 + j2 * 16 + dd * 2 + par] = acc[i];
        }
    }
}

// ---------------- kernel 4: fused ConvTranspose (shortcut 128co + q 64co) ----
template <int NJ>
__device__ __forceinline__ void load_row(float (&r)[NJ], const float* p, bool valid) {
    if (valid) {
        const float4* p4 = (const float4*)p;
#pragma unroll
        for (int q = 0; q < 4; q++) {
            float4 v = __ldg(p4 + q);
            r[4 * q + 0] = v.x; r[4 * q + 1] = v.y; r[4 * q + 2] = v.z; r[4 * q + 3] = v.w;
        }
        if (NJ == 17) r[16] = __ldg(p + 16);
    } else {
#pragma unroll
        for (int q = 0; q < NJ; q++) r[q] = 0.f;
    }
}

template <int XH>
__device__ __forceinline__ void conv_path(float* __restrict__ out, float* sAcc) {
    constexpr int NX = XH ? 32 : 33;
    constexpr int NJ = XH ? 16 : 17;
    constexpr int X0 = XH ? 33 : 0;
    constexpr int JB = XH ? 16 : 0;

    const int y = blockIdx.x;
    const int b = blockIdx.y;
    const int co = threadIdx.x;                        // 0..191
    const float* xrb = g_xr + b * (CC * HWIN);

    float acc[NX];
#pragma unroll
    for (int u = 0; u < NX; u++) acc[u] = 0.f;

    if ((y & 1) == 0) {
        const int iyA = y >> 1;        // tap row kyt=0
        const int iyB = iyA - 1;       // tap row kyt=2
        const bool vA = (iyA <= 31);
        const bool vB = (iyB >= 0);
        for (int c = 0; c < CC; c++) {
            const float* wp = g_wt + (c * 9) * NCO + co;
            float wA0 = wp[0];          float wA1 = wp[NCO];     float wA2 = wp[2 * NCO];
            float wB0 = wp[6 * NCO];    float wB1 = wp[7 * NCO]; float wB2 = wp[8 * NCO];
            float rA[NJ], rB[NJ];
            load_row<NJ>(rA, xrb + (c * 32 + iyA) * 32 + JB, vA);
            load_row<NJ>(rB, xrb + (c * 32 + iyB) * 32 + JB, vB);
#pragma unroll
            for (int u = 0; u < NX; u++) {
                const int x = X0 + u;
                if ((x & 1) == 0) {
                    const int jl = (x >> 1) - JB;
                    if (jl < NJ)  acc[u] += wA0 * rA[jl] + wB0 * rB[jl];
                    if (jl >= 1)  acc[u] += wA2 * rA[jl - 1] + wB2 * rB[jl - 1];
                } else {
                    const int jl = ((x - 1) >> 1) - JB;
                    acc[u] += wA1 * rA[jl] + wB1 * rB[jl];
                }
            }
        }
    } else {
        const int iyC = y >> 1;        // tap row kyt=1, always valid
        for (int c = 0; c < CC; c++) {
            const float* wp = g_wt + (c * 9) * NCO + co;
            float w0 = wp[3 * NCO], w1 = wp[4 * NCO], w2 = wp[5 * NCO];
            float rC[NJ];
            load_row<NJ>(rC, xrb + (c * 32 + iyC) * 32 + JB, true);
#pragma unroll
            for (int u = 0; u < NX; u++) {
                const int x = X0 + u;
                if ((x & 1) == 0) {
                    const int jl = (x >> 1) - JB;
                    if (jl < NJ)  acc[u] += w0 * rC[jl];
                    if (jl >= 1)  acc[u] += w2 * rC[jl - 1];
                } else {
                    const int jl = ((x - 1) >> 1) - JB;
                    acc[u] += w1 * rC[jl];
                }
            }
        }
    }

    // smem transpose -> coalesced stores
#pragma unroll
    for (int u = 0; u < NX; u++) sAcc[co * 33 + u] = acc[u];
    __syncthreads();
    const int total = NCO * NX;
    for (int i = threadIdx.x; i < total; i += NCO) {
        int c2 = i / NX, u2 = i - c2 * NX;
        float v = sAcc[c2 * 33 + u2];
        int n = y * 65 + (X0 + u2);
        if (c2 < 128) out[(b * 128 + c2) * NQ + n] = v;
        else          g_q[(b * 64 + (c2 - 128)) * NQ + n] = v;
    }
}

__global__ void __launch_bounds__(192) convt_kernel(float* __restrict__ out) {
    __shared__ float sAcc[NCO * 33];
    if (blockIdx.z == 0) conv_path<0>(out, sAcc);
    else                 conv_path<1>(out, sAcc);
}

// ---------------- kernel 5: fused attention (online softmax, f32x2) ---------
__global__ void __launch_bounds__(256) attn_kernel() {
    __shared__ float4 sk[1024];   // 256 key-pairs * 16 floats = 16KB
    __shared__ float4 sv[1024];
    const int qt = blockIdx.x, h = blockIdx.y, b = blockIdx.z;
    const int t = threadIdx.x;
    const int n = qt * 256 + t;
    const bool act = (n < NQ);

    // fold 1/sqrt(dk) * log2(e) into q
    const float sc = 0.35355339059327373f * 1.4426950408889634f;
    ull q2[8];
#pragma unroll
    for (int d = 0; d < 8; d++) {
        float qv = act ? g_q[(b * 64 + h * 8 + d) * NQ + n] * sc : 0.f;
        q2[d] = pk2(qv, qv);
    }
    float m = -__int_as_float(0x7f800000);  // -inf
    float l = 0.f;
    ull acc2[8];
#pragma unroll
    for (int d = 0; d < 8; d++) acc2[d] = 0ull;

    const float4* gk = (const float4*)(g_kp + (b * 8 + h) * 8192);
    const float4* gv = (const float4*)(g_vp + (b * 8 + h) * 8192);

    for (int ch = 0; ch < 2; ch++) {
        __syncthreads();
        for (int i = t; i < 1024; i += 256) {
            sk[i] = gk[ch * 1024 + i];
            sv[i] = gv[ch * 1024 + i];
        }
        __syncthreads();
        const ulonglong2* k2 = (const ulonglong2*)sk;
        const ulonglong2* v2 = (const ulonglong2*)sv;
        for (int j2 = 0; j2 < 256; j2++) {
            ulonglong2 ka = k2[j2 * 4 + 0];
            ulonglong2 kb = k2[j2 * 4 + 1];
            ulonglong2 kc = k2[j2 * 4 + 2];
            ulonglong2 kd = k2[j2 * 4 + 3];
            ull s2 = fmul2(q2[0], ka.x);
            s2 = ffma2(q2[1], ka.y, s2);
            s2 = ffma2(q2[2], kb.x, s2);
            s2 = ffma2(q2[3], kb.y, s2);
            s2 = ffma2(q2[4], kc.x, s2);
            s2 = ffma2(q2[5], kc.y, s2);
            s2 = ffma2(q2[6], kd.x, s2);
            s2 = ffma2(q2[7], kd.y, s2);
            float s0, s1; upk2(s2, s0, s1);
            float mx = fmaxf(s0, s1);
            if (mx > m) {
                float corr = ex2f(m - mx);
                m = mx;
                l *= corr;
                ull c2 = pk2(corr, corr);
#pragma unroll
                for (int d = 0; d < 8; d++) acc2[d] = fmul2(acc2[d], c2);
            }
            float p0 = ex2f(s0 - m);
            float p1 = ex2f(s1 - m);
            l += p0 + p1;
            ull p2 = pk2(p0, p1);
            ulonglong2 va = v2[j2 * 4 + 0];
            ulonglong2 vb = v2[j2 * 4 + 1];
            ulonglong2 vc = v2[j2 * 4 + 2];
            ulonglong2 vd = v2[j2 * 4 + 3];
            acc2[0] = ffma2(p2, va.x, acc2[0]);
            acc2[1] = ffma2(p2, va.y, acc2[1]);
            acc2[2] = ffma2(p2, vb.x, acc2[2]);
            acc2[3] = ffma2(p2, vb.y, acc2[3]);
            acc2[4] = ffma2(p2, vc.x, acc2[4]);
            acc2[5] = ffma2(p2, vc.y, acc2[5]);
            acc2[6] = ffma2(p2, vd.x, acc2[6]);
            acc2[7] = ffma2(p2, vd.y, acc2[7]);
        }
    }
    if (act) {
        float inv = 1.f / l;
#pragma unroll
        for (int d = 0; d < 8; d++) {
            float a0, a1; upk2(acc2[d], a0, a1);
            g_attO[(b * 64 + h * 8 + d) * NQ + n] = (a0 + a1) * inv;
        }
    }
}

// ---------------- kernel 6: output projection + residual add -----------------
__global__ void __launch_bounds__(256) proj_kernel(
    const float* __restrict__ w_o, float* __restrict__ out)
{
    __shared__ float sw[128 * 64];
    for (int i = threadIdx.x; i < 8192; i += 256) sw[i] = w_o[i];
    __syncthreads();

    const int b = blockIdx.y;
    const int nl = threadIdx.x & 63;
    const int cog = threadIdx.x >> 6;                  // 0..3 (32 co each)
    const int n = blockIdx.x * 64 + nl;
    if (n >= NQ) return;

    float a[64];
#pragma unroll
    for (int d = 0; d < 64; d++) a[d] = g_attO[(b * 64 + d) * NQ + n];

    for (int c0 = 0; c0 < 32; c0++) {
        int co = cog * 32 + c0;
        const float4* wr = (const float4*)(sw + co * 64);
        float s = 0.f;
#pragma unroll
        for (int dq = 0; dq < 16; dq++) {
            float4 w4 = wr[dq];
            s += w4.x * a[dq * 4 + 0] + w4.y * a[dq * 4 + 1]
               + w4.z * a[dq * 4 + 2] + w4.w * a[dq * 4 + 3];
        }
        int oi = (b * 128 + co) * NQ + n;
        out[oi] += s;
    }
}

// ---------------- launcher ---------------------------------------------------
extern "C" void kernel_launch(void* const* d_in, const int* in_sizes, int n_in,
                              void* d_out, int out_size)
{
    const float* x     = (const float*)d_in[0];
    const float* gamma = (const float*)d_in[1];
    const float* beta  = (const float*)d_in[2];
    const float* rmean = (const float*)d_in[3];
    const float* rvar  = (const float*)d_in[4];
    const float* w_sc  = (const float*)d_in[5];
    const float* w_q   = (const float*)d_in[6];
    const float* w_k   = (const float*)d_in[7];
    const float* w_v   = (const float*)d_in[8];
    const float* w_o   = (const float*)d_in[9];
    float* out = (float*)d_out;

    bn_kernel<<<4096, 256>>>(x, gamma, beta, rmean, rvar);
    repack_kernel<<<1728, 256>>>(w_sc, w_q);
    kv_kernel<<<dim3(32, 4), 256>>>(w_k, w_v);
    convt_kernel<<<dim3(65, 4, 2), 192>>>(out);
    attn_kernel<<<dim3(17, 8, 4), 256>>>();
    proj_kernel<<<dim3(67, 4), 256>>>(w_o, out);
}